// round 1
// baseline (speedup 1.0000x reference)
#include <cuda_runtime.h>
#include <cuda_bf16.h>
#include <cstdint>

// Problem constants
#define HH 256
#define WW 256
#define CC 64
#define BB 2
#define NNODES (BB * HH * WW)   // 131072
#define NEG_SLOPE 0.2f

// Scratch (device globals — no allocation allowed)
__device__ float g_hfeat[(size_t)NNODES * CC];   // node-major [node][c]
__device__ float g_asrc[NNODES];
__device__ float g_adst[NNODES];

// ---------------------------------------------------------------------------
// Kernel 1: hfeat = (x + pe) @ lin_w ; a_src = hfeat@att_src ; a_dst = hfeat@att_dst
// One block = 64 consecutive x-positions of one (b, y) row.
// ---------------------------------------------------------------------------
__global__ __launch_bounds__(256) void gat_k1(
    const float* __restrict__ x,
    const float* __restrict__ pos_w,
    const float* __restrict__ pos_b,
    const float* __restrict__ lin_w,
    const float* __restrict__ att_src,
    const float* __restrict__ att_dst)
{
    __shared__ float xs[64 * 68];    // [node][k], pad 68 for conflict-free float4
    __shared__ float lwT[64 * 68];   // [co][k], transposed lin_w
    __shared__ float as_sh[64], ad_sh[64];
    __shared__ float pw0[64], pw1[64], pb_sh[64];

    const int tid  = threadIdx.x;
    const int tile = blockIdx.x;          // 0..2047
    const int b    = tile >> 10;          // 1024 tiles per batch (256 rows * 4)
    const int rem  = tile & 1023;
    const int y    = rem >> 2;
    const int x0   = (rem & 3) << 6;

    // stage lin_w transposed: lwT[co][k] = lin_w[k*64 + co]
    for (int i = tid; i < 4096; i += 256) {
        int k = i >> 6, co = i & 63;
        lwT[co * 68 + k] = lin_w[i];
    }
    if (tid < 64) {
        as_sh[tid] = att_src[tid];
        pw0[tid]   = pos_w[tid];
    } else if (tid < 128) {
        int t = tid - 64;
        ad_sh[t] = att_dst[t];
        pw1[t]   = pos_w[64 + t];
    } else if (tid < 192) {
        pb_sh[tid - 128] = pos_b[tid - 128];
    }
    __syncthreads();

    // stage xg = x + pe, transposed to [node][c]
    const float py = -1.0f + 2.0f * (float)y * (1.0f / 255.0f);
    {
        const int xn = tid & 63;
        const float pxv = -1.0f + 2.0f * (float)(x0 + xn) * (1.0f / 255.0f);
        #pragma unroll
        for (int cc = 0; cc < 16; cc++) {
            int c = cc * 4 + (tid >> 6);
            float v = x[(((b * 64 + c) * 256 + y) << 8) + x0 + xn];
            v += py * pw0[c] + pxv * pw1[c] + pb_sh[c];
            xs[xn * 68 + c] = v;
        }
    }
    __syncthreads();

    // GEMM: thread (ng, co) computes hfeat[node = ng*16+j][co], j=0..15
    const int co = tid & 63;
    const int ng = tid >> 6;
    float acc[16];
    #pragma unroll
    for (int j = 0; j < 16; j++) acc[j] = 0.0f;

    for (int k0 = 0; k0 < 64; k0 += 4) {
        float4 w = *(const float4*)&lwT[co * 68 + k0];
        #pragma unroll
        for (int j = 0; j < 16; j++) {
            float4 a = *(const float4*)&xs[(ng * 16 + j) * 68 + k0];
            float s = acc[j];
            s = fmaf(a.x, w.x, s);
            s = fmaf(a.y, w.y, s);
            s = fmaf(a.z, w.z, s);
            s = fmaf(a.w, w.w, s);
            acc[j] = s;
        }
    }

    const int node_base = (b << 16) + (y << 8) + x0;
    #pragma unroll
    for (int j = 0; j < 16; j++) {
        g_hfeat[(size_t)(node_base + ng * 16 + j) * 64 + co] = acc[j];
    }

    // reuse xs as hfeat tile for logit reductions
    __syncthreads();
    #pragma unroll
    for (int j = 0; j < 16; j++) xs[(ng * 16 + j) * 68 + co] = acc[j];
    __syncthreads();

    if (tid < 64) {
        float s = 0.0f, d = 0.0f;
        #pragma unroll 8
        for (int c = 0; c < 64; c++) {
            float h = xs[tid * 68 + c];
            s = fmaf(h, as_sh[c], s);
            d = fmaf(h, ad_sh[c], d);
        }
        g_asrc[node_base + tid] = s;
        g_adst[node_base + tid] = d;
    }
}

// ---------------------------------------------------------------------------
// Kernel 2: per-dst 3x3 stencil softmax + weighted aggregation of hfeat.
// One block = 64 consecutive x-positions of one (b, y) row.
// Channels processed in two halves of 32 to stay <48KB static SMEM.
// ---------------------------------------------------------------------------
__global__ __launch_bounds__(256) void gat_k2(
    const float* __restrict__ bias,
    float* __restrict__ out)
{
    __shared__ float hs[3 * 66 * 36];  // [ry][xi][c_local], pad 36
    __shared__ float as_sh[3 * 66];
    __shared__ float alpha[64 * 9];
    __shared__ float b_sh[64];

    const int tid  = threadIdx.x;
    const int tile = blockIdx.x;
    const int b    = tile >> 10;
    const int rem  = tile & 1023;
    const int y    = rem >> 2;
    const int x0   = (rem & 3) << 6;

    if (tid < 64) b_sh[tid] = bias[tid];

    // stage a_src halo rows
    if (tid < 198) {
        int ry = tid / 66, xi = tid - ry * 66;
        int yy = y - 1 + ry;
        int xg = x0 - 1 + xi;
        float v = 0.0f;
        if ((unsigned)yy < 256u && (unsigned)xg < 256u)
            v = g_asrc[(b << 16) + (yy << 8) + xg];
        as_sh[ry * 66 + xi] = v;
    }

    // stage hfeat half 0 (channels 0..31)
    for (int i = tid; i < 3 * 66 * 32; i += 256) {
        int ry = i / (66 * 32);
        int r2 = i - ry * (66 * 32);
        int xi = r2 >> 5;
        int cl = r2 & 31;
        int yy = y - 1 + ry;
        int xg = x0 - 1 + xi;
        float v = 0.0f;
        if ((unsigned)yy < 256u && (unsigned)xg < 256u)
            v = g_hfeat[((size_t)((b << 16) + (yy << 8) + xg) << 6) + cl];
        hs[(ry * 66 + xi) * 36 + cl] = v;
    }
    __syncthreads();

    // attention weights (64 threads, one per dst node)
    if (tid < 64) {
        const int xl = tid;
        const int xd = x0 + xl;
        const float ad = g_adst[(b << 16) + (y << 8) + xd];
        float e[9];
        float m = -1e30f;
        #pragma unroll
        for (int ry = 0; ry < 3; ry++) {
            int yy = y - 1 + ry;
            #pragma unroll
            for (int cx = 0; cx < 3; cx++) {
                int xsg = xd - 1 + cx;
                int j = ry * 3 + cx;
                if ((unsigned)yy < 256u && (unsigned)xsg < 256u) {
                    float ev = as_sh[ry * 66 + xl + cx] + ad;
                    ev = (ev >= 0.0f) ? ev : NEG_SLOPE * ev;
                    e[j] = ev;
                    m = fmaxf(m, ev);
                } else {
                    e[j] = -1e30f;
                }
            }
        }
        float p[9];
        float s = 0.0f;
        #pragma unroll
        for (int j = 0; j < 9; j++) {
            float pj = (e[j] > -1e29f) ? expf(e[j] - m) : 0.0f;
            p[j] = pj;
            s += pj;
        }
        float inv = 1.0f / s;
        #pragma unroll
        for (int j = 0; j < 9; j++) alpha[xl * 9 + j] = p[j] * inv;
    }
    __syncthreads();

    const int xl = tid & 63;
    const int cg = tid >> 6;   // 0..3
    float al[9];
    #pragma unroll
    for (int j = 0; j < 9; j++) al[j] = alpha[xl * 9 + j];

    // ---- half 0 output (channels 0..31) ----
    #pragma unroll
    for (int cc = 0; cc < 2; cc++) {
        int c0l = (cc * 4 + cg) * 4;     // 0..28
        int cgl = c0l;                   // global channel
        float4 acc;
        acc.x = b_sh[cgl]; acc.y = b_sh[cgl + 1];
        acc.z = b_sh[cgl + 2]; acc.w = b_sh[cgl + 3];
        #pragma unroll
        for (int ry = 0; ry < 3; ry++) {
            #pragma unroll
            for (int cx = 0; cx < 3; cx++) {
                float a = al[ry * 3 + cx];
                float4 h = *(const float4*)&hs[(ry * 66 + xl + cx) * 36 + c0l];
                acc.x = fmaf(a, h.x, acc.x);
                acc.y = fmaf(a, h.y, acc.y);
                acc.z = fmaf(a, h.z, acc.z);
                acc.w = fmaf(a, h.w, acc.w);
            }
        }
        size_t ob = (((size_t)(b * 64 + cgl) * 256 + y) << 8) + x0 + xl;
        out[ob]             = acc.x;
        out[ob + 65536]     = acc.y;
        out[ob + 2 * 65536] = acc.z;
        out[ob + 3 * 65536] = acc.w;
    }
    __syncthreads();

    // stage hfeat half 1 (channels 32..63)
    for (int i = tid; i < 3 * 66 * 32; i += 256) {
        int ry = i / (66 * 32);
        int r2 = i - ry * (66 * 32);
        int xi = r2 >> 5;
        int cl = r2 & 31;
        int yy = y - 1 + ry;
        int xg = x0 - 1 + xi;
        float v = 0.0f;
        if ((unsigned)yy < 256u && (unsigned)xg < 256u)
            v = g_hfeat[((size_t)((b << 16) + (yy << 8) + xg) << 6) + 32 + cl];
        hs[(ry * 66 + xi) * 36 + cl] = v;
    }
    __syncthreads();

    // ---- half 1 output (channels 32..63) ----
    #pragma unroll
    for (int cc = 0; cc < 2; cc++) {
        int c0l = (cc * 4 + cg) * 4;
        int cgl = 32 + c0l;
        float4 acc;
        acc.x = b_sh[cgl]; acc.y = b_sh[cgl + 1];
        acc.z = b_sh[cgl + 2]; acc.w = b_sh[cgl + 3];
        #pragma unroll
        for (int ry = 0; ry < 3; ry++) {
            #pragma unroll
            for (int cx = 0; cx < 3; cx++) {
                float a = al[ry * 3 + cx];
                float4 h = *(const float4*)&hs[(ry * 66 + xl + cx) * 36 + c0l];
                acc.x = fmaf(a, h.x, acc.x);
                acc.y = fmaf(a, h.y, acc.y);
                acc.z = fmaf(a, h.z, acc.z);
                acc.w = fmaf(a, h.w, acc.w);
            }
        }
        size_t ob = (((size_t)(b * 64 + cgl) * 256 + y) << 8) + x0 + xl;
        out[ob]             = acc.x;
        out[ob + 65536]     = acc.y;
        out[ob + 2 * 65536] = acc.z;
        out[ob + 3 * 65536] = acc.w;
    }
}

// ---------------------------------------------------------------------------
extern "C" void kernel_launch(void* const* d_in, const int* in_sizes, int n_in,
                              void* d_out, int out_size)
{
    const float* x       = (const float*)d_in[0];
    const float* pos_w   = (const float*)d_in[1];
    const float* pos_b   = (const float*)d_in[2];
    const float* lin_w   = (const float*)d_in[3];
    const float* att_src = (const float*)d_in[4];
    const float* att_dst = (const float*)d_in[5];
    const float* bias    = (const float*)d_in[6];
    // d_in[7] / d_in[8]: edge lists — structure is a fixed 3x3 stencil, not needed.
    float* out = (float*)d_out;

    gat_k1<<<2048, 256>>>(x, pos_w, pos_b, lin_w, att_src, att_dst);
    gat_k2<<<2048, 256>>>(bias, out);
}